// round 17
// baseline (speedup 1.0000x reference)
#include <cuda_runtime.h>
#include <cuda_fp16.h>
#include <math.h>
#include <stdint.h>

#define D_HIDDEN 1024
#define D_INTER  4096
#define NE       8
#define NTOK     2048
#define NPAIR    (NTOK * 2)
#define GU_ROWS  8192

// per-buffer: AH 16K | AL 16K | B 16K ; two buffers (stride 48K)
#define SM_AH    0
#define SM_AL    16384
#define SM_BB    32768
#define SM_BUF   49152
#define SM_TOK   98304
#define SM_COEF  98816
#define SM_TOTAL 99328

__device__ __forceinline__ uint32_t smem_u32(const void* p) {
    uint32_t a;
    asm("{ .reg .u64 t; cvta.to.shared.u64 t, %1; cvt.u32.u64 %0, t; }" : "=r"(a) : "l"(p));
    return a;
}
#define LDSM_X4(r, addr) \
    asm volatile("ldmatrix.sync.aligned.m8n8.x4.shared.b16 {%0,%1,%2,%3}, [%4];" \
        : "=r"((r)[0]), "=r"((r)[1]), "=r"((r)[2]), "=r"((r)[3]) : "r"(addr))
#define MMAF16(c, a, b0, b1) \
    asm volatile("mma.sync.aligned.m16n8k16.row.col.f32.f16.f16.f32 " \
        "{%0,%1,%2,%3}, {%4,%5,%6,%7}, {%8,%9}, {%0,%1,%2,%3};" \
        : "+f"((c)[0]), "+f"((c)[1]), "+f"((c)[2]), "+f"((c)[3]) \
        : "r"((a)[0]), "r"((a)[1]), "r"((a)[2]), "r"((a)[3]), "r"(b0), "r"(b1))
#define CP16(dst, src) \
    asm volatile("cp.async.cg.shared.global [%0], [%1], 16;" :: "r"(dst), "l"(src))
#define CP_COMMIT() asm volatile("cp.async.commit_group;" ::: "memory")
#define CP_WAIT0()  asm volatile("cp.async.wait_group 0;" ::: "memory")

// fp16 bits of {0,.5,1,1.5,2,3,4,6} and negatives
__device__ __constant__ unsigned short c_lut16[16] = {
    0x0000, 0x3800, 0x3C00, 0x3E00, 0x4000, 0x4200, 0x4400, 0x4600,
    0x8000, 0xB800, 0xBC00, 0xBE00, 0xC000, 0xC200, 0xC400, 0xC600};

__device__ int   g_top_idx[NTOK][2];
__device__ float g_top_w[NTOK][2];
__device__ int   g_count[NE];
__device__ int   g_off[NE];
__device__ int   g_list[NE][NTOK];
__device__ float g_coefs[NE][NTOK];
__device__ unsigned short g_x_h[(size_t)NTOK * D_HIDDEN];
__device__ unsigned short g_x_l[(size_t)NTOK * D_HIDDEN];
__device__ unsigned short g_act[(size_t)NPAIR * D_INTER];
__device__ unsigned short g_gu16[(size_t)NE * GU_ROWS * D_HIDDEN];   // 134 MB fp16 weights
__device__ unsigned short g_dn16[(size_t)NE * D_HIDDEN * D_INTER];   // 67 MB

__global__ void zero_kernel(float* __restrict__ out, int n) {
    int i = blockIdx.x * blockDim.x + threadIdx.x;
    if (i < n) out[i] = 0.0f;
}
__global__ void prep_x_kernel(const float* __restrict__ x) {
    int row = blockIdx.x;
    int c = threadIdx.x * 4;
    float4 f = *(const float4*)(x + (size_t)row * D_HIDDEN + c);
    float v[4] = {f.x, f.y, f.z, f.w};
    unsigned short h[4], l[4];
#pragma unroll
    for (int i = 0; i < 4; i++) {
        __half hh = __float2half_rn(v[i]);
        h[i] = __half_as_ushort(hh);
        l[i] = __half_as_ushort(__float2half_rn(v[i] - __half2float(hh)));
    }
    uint2 ph, pl;
    ph.x = (uint32_t)h[0] | ((uint32_t)h[1] << 16); ph.y = (uint32_t)h[2] | ((uint32_t)h[3] << 16);
    pl.x = (uint32_t)l[0] | ((uint32_t)l[1] << 16); pl.y = (uint32_t)l[2] | ((uint32_t)l[3] << 16);
    *(uint2*)(g_x_h + (size_t)row * D_HIDDEN + c) = ph;
    *(uint2*)(g_x_l + (size_t)row * D_HIDDEN + c) = pl;
}
// prequant v2: one thread = one scale block (16 inflated ints = 32 elems),
// 4 independent int4 loads (MLP=4) + smem byte-LUT + exact power-of-2 HMUL2.
// sbpr = scale blocks per row (threads per row).
__global__ void prequant_kernel(const int* __restrict__ src, const int* __restrict__ scales,
                                unsigned short* __restrict__ dst, int sbpr) {
    __shared__ uint32_t tbl[256];
    const int tid = threadIdx.x;
    {
        uint32_t lo = c_lut16[tid & 15], hi = c_lut16[(tid >> 4) & 15];
        tbl[tid] = lo | (hi << 16);
    }
    __syncthreads();
    size_t g = (size_t)blockIdx.x * 256 + tid;       // one scale block
    const int4* sp = (const int4*)src + g * 4;       // 16 ints
    int4 q0 = sp[0], q1 = sp[1], q2 = sp[2], q3 = sp[3];
    int s = scales[g];
    (void)sbpr;
    uint32_t shb = ((uint32_t)(s - 112) << 10);
    shb |= shb << 16;
    __half2 sp2 = *(__half2*)&shb;
    uint4* dp = (uint4*)(dst + g * 32);
    int4 qs[4] = {q0, q1, q2, q3};
#pragma unroll
    for (int i = 0; i < 4; i++) {
        int4 q = qs[i];
        __half2 r0 = __hmul2(*(__half2*)&tbl[(uint32_t)q.x & 255u], sp2);
        __half2 r1 = __hmul2(*(__half2*)&tbl[(uint32_t)q.y & 255u], sp2);
        __half2 r2 = __hmul2(*(__half2*)&tbl[(uint32_t)q.z & 255u], sp2);
        __half2 r3 = __hmul2(*(__half2*)&tbl[(uint32_t)q.w & 255u], sp2);
        uint4 o;
        o.x = *(uint32_t*)&r0; o.y = *(uint32_t*)&r1;
        o.z = *(uint32_t*)&r2; o.w = *(uint32_t*)&r3;
        dp[i] = o;
    }
}
__global__ void router_kernel(const float* __restrict__ x,
                              const float* __restrict__ rw,
                              const float* __restrict__ rb) {
    int warp = threadIdx.x >> 5, lane = threadIdx.x & 31;
    int t = blockIdx.x * 8 + warp;
    if (t >= NTOK) return;
    float acc[NE];
#pragma unroll
    for (int e = 0; e < NE; e++) acc[e] = 0.0f;
    const float* xr = x + (size_t)t * D_HIDDEN;
    for (int k = lane; k < D_HIDDEN; k += 32) {
        float xv = xr[k];
#pragma unroll
        for (int e = 0; e < NE; e++) acc[e] += xv * rw[e * D_HIDDEN + k];
    }
#pragma unroll
    for (int e = 0; e < NE; e++)
#pragma unroll
        for (int o = 16; o > 0; o >>= 1) acc[e] += __shfl_xor_sync(0xffffffffu, acc[e], o);
    if (lane == 0) {
        float v[NE];
#pragma unroll
        for (int e = 0; e < NE; e++) v[e] = acc[e] + rb[e];
        int i0 = 0;
#pragma unroll
        for (int e = 1; e < NE; e++) if (v[e] > v[i0]) i0 = e;
        int i1 = -1;
#pragma unroll
        for (int e = 0; e < NE; e++) {
            if (e == i0) continue;
            if (i1 < 0 || v[e] > v[i1]) i1 = e;
        }
        float w1 = expf(v[i1] - v[i0]);
        float inv = 1.0f / (1.0f + w1);
        g_top_idx[t][0] = i0; g_top_idx[t][1] = i1;
        g_top_w[t][0] = inv;  g_top_w[t][1] = w1 * inv;
    }
}
__global__ void compact_kernel() {
    const int e = blockIdx.x, tid = threadIdx.x;
    __shared__ int scan[256];
    __shared__ int sbase;
    if (tid == 0) sbase = 0;
    __syncthreads();
    for (int c = 0; c < NTOK; c += 256) {
        int t = c + tid;
        int flag = (g_top_idx[t][0] == e) || (g_top_idx[t][1] == e);
        float coef = (g_top_idx[t][0] == e) ? g_top_w[t][0] : g_top_w[t][1];
        scan[tid] = flag;
        __syncthreads();
#pragma unroll
        for (int off = 1; off < 256; off <<= 1) {
            int v = (tid >= off) ? scan[tid - off] : 0;
            __syncthreads();
            scan[tid] += v;
            __syncthreads();
        }
        if (flag) {
            int pos = sbase + scan[tid] - 1;
            g_list[e][pos] = t; g_coefs[e][pos] = coef;
        }
        __syncthreads();
        if (tid == 0) sbase += scan[255];
        __syncthreads();
    }
    if (tid == 0) g_count[e] = sbase;
}
__global__ void offsets_kernel() {
    if (threadIdx.x == 0) {
        int r = 0;
#pragma unroll
        for (int e = 0; e < NE; e++) { g_off[e] = r; r += g_count[e]; }
    }
}

// ============================================================
// GEMM1: fp16 hi+lo planes, B via cp.async from prequantized fp16.
// 128x128 tile, BK=64, 8 warps (4M x 2N), warp 32x64, double-buffered.
// ============================================================
__global__ __launch_bounds__(256, 2) void gemm1_kernel(const float* __restrict__ gbias) {
    const int e  = blockIdx.y >> 6;
    const int r0 = (blockIdx.y & 63) << 7;
    const int m0 = blockIdx.x << 7;
    const int cnt = g_count[e];
    if (m0 >= cnt) return;
    const int valid = min(128, cnt - m0);
    const int off = g_off[e];
    extern __shared__ char smem[];
    const uint32_t sb = smem_u32(smem);
    const int tid = threadIdx.x, wid = tid >> 5, lane = tid & 31;
    const int wm = wid & 3, wn = wid >> 2;

    int* stok = (int*)(smem + SM_TOK);
    if (tid < 128) stok[tid] = g_list[e][m0 + (tid < valid ? tid : 0)];
    __syncthreads();

    const int arow = tid >> 1, kh = (tid & 1) << 5;
    const unsigned short* xh = g_x_h + (size_t)stok[arow] * D_HIDDEN + kh;
    const unsigned short* xl = g_x_l + (size_t)stok[arow] * D_HIDDEN + kh;
    const unsigned short* bwp = g_gu16 + (size_t)(e * GU_ROWS + r0 + arow) * D_HIDDEN + kh;
    const uint32_t fbase = (uint32_t)arow << 7;
    const uint32_t frx = ((uint32_t)arow & 7u) << 4;
    uint32_t fo[4];
#pragma unroll
    for (int j = 0; j < 4; j++)
        fo[j] = fbase + ((((uint32_t)(kh + j * 8)) << 1) ^ frx);

    uint32_t aAddr[2], arx[2];
#pragma unroll
    for (int mf = 0; mf < 2; mf++) {
        int r = wm * 32 + mf * 16 + (lane & 15);
        aAddr[mf] = sb + ((uint32_t)r << 7);
        arx[mf] = ((uint32_t)r & 7u) << 4;
    }
    const uint32_t a_cb = (uint32_t)(lane >> 4) << 4;
    uint32_t bAddr[4], brxv[4];
#pragma unroll
    for (int g = 0; g < 4; g++) {
        int r = wn * 64 + g * 16 + ((lane >> 4) << 3) + (lane & 7);
        bAddr[g] = sb + SM_BB + ((uint32_t)r << 7);
        brxv[g] = ((uint32_t)r & 7u) << 4;
    }
    const uint32_t b_cb = ((uint32_t)(lane >> 3) & 1u) << 4;

    float acc[2][8][4];
#pragma unroll
    for (int mf = 0; mf < 2; mf++)
#pragma unroll
        for (int nf = 0; nf < 8; nf++)
#pragma unroll
            for (int j = 0; j < 4; j++) acc[mf][nf][j] = 0.0f;

#pragma unroll
    for (int j = 0; j < 4; j++) {
        CP16(sb + SM_AH + fo[j], xh + j * 8);
        CP16(sb + SM_AL + fo[j], xl + j * 8);
        CP16(sb + SM_BB + fo[j], bwp + j * 8);
    }
    CP_COMMIT();

    const int NKB = D_HIDDEN / 64;
    for (int kb = 0; kb < NKB; kb++) {
        const uint32_t bo = (uint32_t)(kb & 1) * SM_BUF;
        CP_WAIT0();
        __syncthreads();
        if (kb + 1 < NKB) {
            const uint32_t bo2 = (uint32_t)((kb + 1) & 1) * SM_BUF;
#pragma unroll
            for (int j = 0; j < 4; j++) {
                CP16(sb + bo2 + SM_AH + fo[j], xh + (kb + 1) * 64 + j * 8);
                CP16(sb + bo2 + SM_AL + fo[j], xl + (kb + 1) * 64 + j * 8);
                CP16(sb + bo2 + SM_BB + fo[j], bwp + (kb + 1) * 64 + j * 8);
            }
            CP_COMMIT();
        }
#pragma unroll
        for (int ks = 0; ks < 4; ks++) {
            uint32_t acol = (uint32_t)ks * 32 + a_cb;
            uint32_t bcol = (uint32_t)ks * 32 + b_cb;
            uint32_t Ah[2][4], Al[2][4], Bf[4][4];
#pragma unroll
            for (int mf = 0; mf < 2; mf++) {
                LDSM_X4(Ah[mf], aAddr[mf] + bo + SM_AH + (acol ^ arx[mf]));
                LDSM_X4(Al[mf], aAddr[mf] + bo + SM_AL + (acol ^ arx[mf]));
            }
#pragma unroll
            for (int g = 0; g < 4; g++) LDSM_X4(Bf[g], bAddr[g] + bo + (bcol ^ brxv[g]));
#pragma unroll
            for (int mf = 0; mf < 2; mf++)
#pragma unroll
                for (int nf = 0; nf < 8; nf++) {
                    uint32_t bb0 = Bf[nf >> 1][(nf & 1) * 2];
                    uint32_t bb1 = Bf[nf >> 1][(nf & 1) * 2 + 1];
                    MMAF16(acc[mf][nf], Ah[mf], bb0, bb1);
                    MMAF16(acc[mf][nf], Al[mf], bb0, bb1);
                }
        }
    }
    __syncthreads();

    // epilogue: bias + SwiGLU -> stage -> single fp16 act plane
    const float* gb = gbias + (size_t)e * GU_ROWS;
    unsigned short* stage = (unsigned short*)smem;
#pragma unroll
    for (int mf = 0; mf < 2; mf++)
#pragma unroll
        for (int nf = 0; nf < 8; nf++) {
            int gucol = r0 + wn * 64 + nf * 8 + (lane & 3) * 2;
            float bg = gb[gucol], bu = gb[gucol + 1];
            int cl = wn * 32 + nf * 4 + (lane & 3);
#pragma unroll
            for (int rr = 0; rr < 2; rr++) {
                int r = wm * 32 + mf * 16 + (lane >> 2) + rr * 8;
                float gate = acc[mf][nf][rr * 2 + 0] + bg;
                float up   = acc[mf][nf][rr * 2 + 1] + bu;
                gate = fminf(gate, 7.0f);
                up = fminf(fmaxf(up, -7.0f), 7.0f);
                float sg = 1.0f / (1.0f + __expf(-1.702f * gate));
                float a = (up + 1.0f) * (gate * sg);
                stage[r * 72 + cl] = __half_as_ushort(__float2half_rn(a));
            }
        }
    __syncthreads();
    {
        int row = tid >> 1;
        if (row < valid) {
            size_t gbase = (size_t)(off + m0 + row) * D_INTER + (r0 >> 1) + (tid & 1) * 32;
            uint4* dh = (uint4*)(g_act + gbase);
            const uint4* shp = (const uint4*)(stage + row * 72 + (tid & 1) * 32);
#pragma unroll
            for (int i = 0; i < 4; i++) dh[i] = shp[i];
        }
    }
}

// ============================================================
// GEMM2 (single fp16 plane, B via cp.async from prequantized fp16)
// ============================================================
__global__ __launch_bounds__(256, 2) void gemm2_kernel(
    const float* __restrict__ dbias, float* __restrict__ out) {
    const int e  = blockIdx.y >> 3;
    const int r0 = (blockIdx.y & 7) << 7;
    const int m0 = blockIdx.x << 7;
    const int cnt = g_count[e];
    if (m0 >= cnt) return;
    const int valid = min(128, cnt - m0);
    const int off = g_off[e];
    extern __shared__ char smem[];
    const uint32_t sb = smem_u32(smem);
    const int tid = threadIdx.x, wid = tid >> 5, lane = tid & 31;
    const int wm = wid & 3, wn = wid >> 2;

    int* stok = (int*)(smem + SM_TOK);
    float* scoef = (float*)(smem + SM_COEF);
    if (tid < 128) {
        int mm = (tid < valid) ? tid : 0;
        stok[tid] = g_list[e][m0 + mm];
        scoef[tid] = g_coefs[e][m0 + mm];
    }
    __syncthreads();

    const int arow = tid >> 1, kh = (tid & 1) << 5;
    const int pr = off + m0 + ((arow < valid) ? arow : 0);
    const unsigned short* ah = g_act + (size_t)pr * D_INTER + kh;
    const unsigned short* bwp = g_dn16 + (size_t)(e * D_HIDDEN + r0 + arow) * D_INTER + kh;
    const uint32_t fbase = (uint32_t)arow << 7;
    const uint32_t frx = ((uint32_t)arow & 7u) << 4;
    uint32_t fo[4];
#pragma unroll
    for (int j = 0; j < 4; j++)
        fo[j] = fbase + ((((uint32_t)(kh + j * 8)) << 1) ^ frx);

    uint32_t aAddr[2], arx[2];
#pragma unroll
    for (int mf = 0; mf < 2; mf++) {
        int r = wm * 32 + mf * 16 + (lane & 15);
        aAddr[mf] = sb + ((uint32_t)r << 7);
        arx[mf] = ((uint32_t)r & 7u) << 4;
    }
    const uint32_t a_cb = (uint32_t)(lane >> 4) << 4;
    uint32_t bAddr[4], brxv[4];
#pragma unroll
    for (int g = 0; g < 4; g++) {
        int r = wn * 64 + g * 16 + ((lane >> 4) << 3) + (lane & 7);
        bAddr[g] = sb + SM_BB + ((uint32_t)r << 7);
        brxv[g] = ((uint32_t)r & 7u) << 4;
    }
    const uint32_t b_cb = ((uint32_t)(lane >> 3) & 1u) << 4;

    float acc[2][8][4];
#pragma unroll
    for (int mf = 0; mf < 2; mf++)
#pragma unroll
        for (int nf = 0; nf < 8; nf++)
#pragma unroll
            for (int j = 0; j < 4; j++) acc[mf][nf][j] = 0.0f;

#pragma unroll
    for (int j = 0; j < 4; j++) {
        CP16(sb + SM_AH + fo[j], ah + j * 8);
        CP16(sb + SM_BB + fo[j], bwp + j * 8);
    }
    CP_COMMIT();

    const int NKB = D_INTER / 64;
    for (int kb = 0; kb < NKB; kb++) {
        const uint32_t bo = (uint32_t)(kb & 1) * SM_BUF;
        CP_WAIT0();
        __syncthreads();
        if (kb + 1 < NKB) {
            const uint32_t bo2 = (uint32_t)((kb + 1) & 1) * SM_BUF;
#pragma unroll
            for (int j = 0; j < 4; j++) {
                CP16(sb + bo2 + SM_AH + fo[j], ah + (kb + 1) * 64 + j * 8);
                CP16(sb + bo2 + SM_BB + fo[j], bwp + (kb + 1) * 64 + j * 8);
            }
            CP_COMMIT();
        }
#pragma unroll
        for (int ks = 0; ks < 4; ks++) {
            uint32_t acol = (uint32_t)ks * 32 + a_cb;
            uint32_t bcol = (uint32_t)ks * 32 + b_cb;
            uint32_t Ah[2][4], Bf[4][4];
#pragma unroll
            for (int mf = 0; mf < 2; mf++)
                LDSM_X4(Ah[mf], aAddr[mf] + bo + SM_AH + (acol ^ arx[mf]));
#pragma unroll
            for (int g = 0; g < 4; g++) LDSM_X4(Bf[g], bAddr[g] + bo + (bcol ^ brxv[g]));
#pragma unroll
            for (int mf = 0; mf < 2; mf++)
#pragma unroll
                for (int nf = 0; nf < 8; nf++) {
                    uint32_t bb0 = Bf[nf >> 1][(nf & 1) * 2];
                    uint32_t bb1 = Bf[nf >> 1][(nf & 1) * 2 + 1];
                    MMAF16(acc[mf][nf], Ah[mf], bb0, bb1);
                }
        }
    }

    const float* db = dbias + (size_t)e * D_HIDDEN;
#pragma unroll
    for (int mf = 0; mf < 2; mf++)
#pragma unroll
        for (int nf = 0; nf < 8; nf++) {
            int gcol = r0 + wn * 64 + nf * 8 + (lane & 3) * 2;
            float b0 = db[gcol], b1 = db[gcol + 1];
#pragma unroll
            for (int rr = 0; rr < 2; rr++) {
                int m = wm * 32 + mf * 16 + (lane >> 2) + rr * 8;
                if (m < valid) {
                    float coef = scoef[m];
                    float* orow = out + (size_t)stok[m] * D_HIDDEN;
                    atomicAdd(orow + gcol,     coef * (acc[mf][nf][rr * 2 + 0] + b0));
                    atomicAdd(orow + gcol + 1, coef * (acc[mf][nf][rr * 2 + 1] + b1));
                }
            }
        }
}

// ============================================================
extern "C" void kernel_launch(void* const* d_in, const int* in_sizes, int n_in,
                              void* d_out, int out_size) {
    const float* x     = (const float*)d_in[0];
    const float* rw    = (const float*)d_in[1];
    const float* rb    = (const float*)d_in[2];
    const float* gbias = (const float*)d_in[3];
    const float* dbias = (const float*)d_in[4];
    const int*   gub   = (const int*)d_in[5];
    const int*   gus   = (const int*)d_in[6];
    const int*   dnb   = (const int*)d_in[7];
    const int*   dns   = (const int*)d_in[8];
    float* out = (float*)d_out;

    cudaFuncSetAttribute(gemm1_kernel, cudaFuncAttributeMaxDynamicSharedMemorySize, SM_TOTAL);
    cudaFuncSetAttribute(gemm2_kernel, cudaFuncAttributeMaxDynamicSharedMemorySize, SM_TOTAL);
    unsigned short* gu16; cudaGetSymbolAddress((void**)&gu16, g_gu16);
    unsigned short* dn16; cudaGetSymbolAddress((void**)&dn16, g_dn16);

    zero_kernel<<<(out_size + 255) / 256, 256>>>(out, out_size);
    prep_x_kernel<<<NTOK, 256>>>(x);
    // gu: 65536 rows x 32 scale blocks = 2,097,152 threads = 8192 blocks
    prequant_kernel<<<8192, 256>>>(gub, gus, gu16, 32);
    // dn: 8192 rows x 128 scale blocks = 1,048,576 threads = 4096 blocks
    prequant_kernel<<<4096, 256>>>(dnb, dns, dn16, 128);
    router_kernel<<<NTOK / 8, 256>>>(x, rw, rb);
    compact_kernel<<<NE, 256>>>();
    offsets_kernel<<<1, 32>>>();
    gemm1_kernel<<<dim3(16, NE * 64), 256, SM_TOTAL>>>(gbias);
    gemm2_kernel<<<dim3(16, NE * 8), 256, SM_TOTAL>>>(dbias, out);
}